// round 16
// baseline (speedup 1.0000x reference)
#include <cuda_runtime.h>
#include <cuda_bf16.h>
#include <cstdint>
#include <cstddef>

// ---------------------------------------------------------------------------
// pre[b,o,d] = sum_{h,f} W[o, h*64+f] * x[b,h,d] * inp[b,f,d] + bias[o]
// x_next = relu(pre);  out[:, off+o] = sum_d relu(pre);  3 chained layers.
// B=512, F=64, D=32, O=128.
//
// Round-16 == round-15 resubmission (infra failure, kernel never ran):
//  - ONE merged prep kernel (block-range dispatch) instead of 4 launches.
//  - 320 threads: 8 consumer warps (m32xn64) + 2 producer warps -> reg
//    ceiling 204, spent on kk-level fragment double-buffering in consumers
//    (collapse per-tile LDSM latency exposure from 4 windows to 1).
//  - Fully fused L0->L1->L2 per CTA, x_next in SMEM, layer-0 symmetry fold,
//    3-MMA bf16 split, 2-stage mbarrier pipeline.
// ---------------------------------------------------------------------------

#define SW128(o) ((o) ^ (((o) >> 3) & 0x70))

#define K0SYM   2112
#define K0REAL  2080
#define NT0     33
#define NT12    128

__device__ uint4 g_W0[33 * 32768 / 16];
__device__ uint4 g_W1[128 * 8192 * 4 / 16];
__device__ uint4 g_W2[128 * 8192 * 4 / 16];
__device__ unsigned short g_pair[K0SYM];

__device__ __forceinline__ uint32_t smem_u32(const void* p) {
    uint32_t a;
    asm("{ .reg .u64 t; cvta.to.shared.u64 t, %1; cvt.u32.u64 %0, t; }"
        : "=r"(a) : "l"(p));
    return a;
}

__device__ __forceinline__ void split2(float z0, float z1,
                                       uint32_t& hi, uint32_t& lo) {
    __nv_bfloat162 h = __floats2bfloat162_rn(z0, z1);
    float2 hf = __bfloat1622float2(h);
    __nv_bfloat162 l = __floats2bfloat162_rn(z0 - hf.x, z1 - hf.y);
    hi = reinterpret_cast<uint32_t&>(h);
    lo = reinterpret_cast<uint32_t&>(l);
}

__device__ __forceinline__ void ldsm4(uint32_t r[4], uint32_t addr) {
    asm volatile("ldmatrix.sync.aligned.m8n8.x4.shared.b16 {%0,%1,%2,%3}, [%4];"
                 : "=r"(r[0]), "=r"(r[1]), "=r"(r[2]), "=r"(r[3]) : "r"(addr));
}

__device__ __forceinline__ void mma_bf16(float c[4], const uint32_t a[4],
                                         uint32_t b0, uint32_t b1) {
    asm volatile(
        "mma.sync.aligned.m16n8k16.row.col.f32.bf16.bf16.f32 "
        "{%0,%1,%2,%3}, {%4,%5,%6,%7}, {%8,%9}, {%0,%1,%2,%3};"
        : "+f"(c[0]), "+f"(c[1]), "+f"(c[2]), "+f"(c[3])
        : "r"(a[0]), "r"(a[1]), "r"(a[2]), "r"(a[3]), "r"(b0), "r"(b1));
}

#define MBAR_INIT(a, c) \
    asm volatile("mbarrier.init.shared.b64 [%0], %1;" :: "r"(a), "r"(c) : "memory")
#define MBAR_ARRIVE(a) \
    asm volatile("mbarrier.arrive.release.cta.shared::cta.b64 _, [%0];" :: "r"(a) : "memory")
#define MBAR_WAIT(a, p) do { uint32_t _m = (a); uint32_t _p = (p); uint32_t _d;      \
    asm volatile("{\n\t.reg .pred q;\n\t"                                            \
        "mbarrier.try_wait.parity.acquire.cta.shared::cta.b64 q, [%1], %2;\n\t"      \
        "selp.b32 %0,1,0,q;\n\t}" : "=r"(_d) : "r"(_m), "r"(_p) : "memory");         \
    if (!_d) {                                                                       \
        asm volatile("{\n\t.reg .pred q;\n\t"                                        \
            "WL%=:\n\t"                                                              \
            "mbarrier.try_wait.parity.acquire.cta.shared::cta.b64 q, [%0], %1, 0x989680;\n\t" \
            "@q bra.uni WD%=;\n\t"                                                   \
            "bra.uni WL%=;\n\t"                                                      \
            "WD%=:\n\t}" :: "r"(_m), "r"(_p) : "memory");                            \
    } } while (0)

// --------------------------- merged prep kernel -----------------------------
// Block ranges: [0,132) W0-fold; [132,644) W1; [644,1156) W2; [1156,1165) pairs
#define PREP_BLOCKS 1165

__device__ __forceinline__ void prep_chunk(const float* __restrict__ Wrow8,
                                           char* __restrict__ base,
                                           int o, int k0) {
    const float4* src = (const float4*)Wrow8;
    float4 v0 = src[0], v1 = src[1];
    float zf[8] = {v0.x, v0.y, v0.z, v0.w, v1.x, v1.y, v1.z, v1.w};
    uint32_t hi[4], lo[4];
#pragma unroll
    for (int p = 0; p < 4; p++) split2(zf[2 * p], zf[2 * p + 1], hi[p], lo[p]);
    char* tile = base + (size_t)(k0 >> 6) * 32768;
    uint32_t off = SW128((uint32_t)(o * 128 + (k0 & 63) * 2));
    *(uint4*)(tile + off)         = make_uint4(hi[0], hi[1], hi[2], hi[3]);
    *(uint4*)(tile + 16384 + off) = make_uint4(lo[0], lo[1], lo[2], lo[3]);
}

__global__ __launch_bounds__(256)
void prep_all(const float* __restrict__ W0,
              const float* __restrict__ W1,
              const float* __restrict__ W2)
{
    const int blk = blockIdx.x;
    const int t   = threadIdx.x;
    if (blk < 132) {
        // W0 symmetry fold (pairs computed inline)
        int idx = blk * 256 + t;
        if (idx >= 128 * (K0SYM / 8)) return;
        int o  = idx / (K0SYM / 8);
        int k0 = (idx % (K0SYM / 8)) * 8;
        const float* Wo = W0 + (size_t)o * 4096;
        float zf[8];
#pragma unroll
        for (int tt = 0; tt < 8; tt++) {
            int k = k0 + tt;
            float c = 0.f;
            if (k < K0REAL) {
                int i = 0, base = 0;
                while (base + (64 - i) <= k) { base += 64 - i; i++; }
                int j = i + (k - base);
                c = (i == j) ? Wo[i * 65] : (Wo[i * 64 + j] + Wo[j * 64 + i]);
            }
            zf[tt] = c;
        }
        uint32_t hi[4], lo[4];
#pragma unroll
        for (int p = 0; p < 4; p++) split2(zf[2 * p], zf[2 * p + 1], hi[p], lo[p]);
        char* tile = (char*)g_W0 + (size_t)(k0 >> 6) * 32768;
        uint32_t off = SW128((uint32_t)(o * 128 + (k0 & 63) * 2));
        *(uint4*)(tile + off)         = make_uint4(hi[0], hi[1], hi[2], hi[3]);
        *(uint4*)(tile + 16384 + off) = make_uint4(lo[0], lo[1], lo[2], lo[3]);
    } else if (blk < 1156) {
        // W1 / W2 split
        const bool is1 = blk < 644;
        const float* W  = is1 ? W1 : W2;
        char* dst       = (char*)(is1 ? g_W1 : g_W2);
        int idx = (blk - (is1 ? 132 : 644)) * 256 + t;   // < 131072
        int o = idx >> 10;
        int k = (idx & 1023) * 8;
        prep_chunk(W + (size_t)o * 8192 + k, dst, o, k);
    } else {
        // pair table (used by fused3's SYM producer)
        int k = (blk - 1156) * 256 + t;
        if (k >= K0SYM) return;
        if (k < K0REAL) {
            int i = 0, base = 0;
            while (base + (64 - i) <= k) { base += 64 - i; i++; }
            int j = i + (k - base);
            g_pair[k] = (unsigned short)(i | (j << 8));
        } else {
            g_pair[k] = 0;
        }
    }
}

// --------------------------- fused 3-layer kernel ---------------------------
// SMEM: [0,32768) inp_s; [32768,98304) xbuf; [98304 + s*65536) stages;
//       [229376,229408) mbarriers
#define XBUF_OFF   32768
#define STAGE_OFF  98304
#define MB_OFF     229376
#define SMEM_TOTAL 229408

__global__ __launch_bounds__(320, 1)
void fused3(const float* __restrict__ inp,
            const float* __restrict__ bias0,
            const float* __restrict__ bias1,
            const float* __restrict__ bias2,
            float* __restrict__ out)
{
    extern __shared__ char smem[];
    const uint32_t sb = smem_u32(smem);
    float* inp_s = (float*)smem;
    float* xbuf  = (float*)(smem + XBUF_OFF);
    const int tid  = threadIdx.x;
    const int lane = tid & 31;
    const int w    = tid >> 5;
    const int b0   = blockIdx.x * 4;

    const uint32_t FULLB  = sb + MB_OFF;        // +8*s
    const uint32_t EMPTYB = sb + MB_OFF + 16;   // +8*s

    if (tid == 0) {
#pragma unroll
        for (int s = 0; s < 2; s++) {
            MBAR_INIT(FULLB + 8 * s, 2);     // 2 producer warps
            MBAR_INIT(EMPTYB + 8 * s, 8);    // 8 consumer warps
        }
    }
    {   // stage inp (2048 float4, 320 threads)
        const float4* src = (const float4*)(inp + (size_t)b0 * 2048);
        float4* dst = (float4*)inp_s;
        for (int i = tid; i < 2048; i += 320) dst[i] = src[i];
    }
    __syncthreads();

    if (w >= 8) {
        // ==================== PRODUCERS (warps 8-9, 64 threads) ====================
        const int ptid = tid - 256;                // 0..63; columns ptid, ptid+64
        int gt = 0;

        auto produce = [&](const char* gW, int ntiles, bool sym) {
            for (int it = 0; it < ntiles; ++it, ++gt) {
                const int s = gt & 1;
                if (gt >= 2) MBAR_WAIT(EMPTYB + 8 * s,
                                       (uint32_t)(((gt >> 1) - 1) & 1));
                // W tile: 64 threads x 512 B via cp.async
                {
                    uint32_t dsb = sb + STAGE_OFF + s * 65536 + ptid * 16;
                    const char* srcW = gW + (size_t)it * 32768 + ptid * 16;
#pragma unroll
                    for (int i = 0; i < 32; i++)
                        asm volatile("cp.async.cg.shared.global [%0], [%1], 16;"
                                     :: "r"(dsb + i * 1024), "l"(srcW + i * 1024));
                    asm volatile("cp.async.commit_group;");
                }
                // Z tile: two n-columns per thread
                char* zp = smem + STAGE_OFF + s * 65536 + 32768;
#pragma unroll
                for (int nn = 0; nn < 2; nn++) {
                    const int n  = ptid + nn * 64;
                    const int bq = n >> 5;
                    const int dd = n & 31;
                    const float* ip = inp_s + (size_t)bq * 2048 + dd;
                    const uint32_t zrow  = (uint32_t)n * 128;
                    const uint32_t zmask = (uint32_t)((n & 7) << 4);
                    if (sym) {
#pragma unroll
                        for (int i = 0; i < 8; i++) {
                            float z[8];
#pragma unroll
                            for (int j = 0; j < 8; j++) {
                                int pr = __ldg(&g_pair[it * 64 + i * 8 + j]);
                                z[j] = ip[(pr & 255) * 32] * ip[(pr >> 8) * 32];
                            }
                            uint32_t hi[4], lo[4];
#pragma unroll
                            for (int p = 0; p < 4; p++)
                                split2(z[2 * p], z[2 * p + 1], hi[p], lo[p]);
                            uint32_t off = zrow + ((16u * i) ^ zmask);
                            *(uint4*)(zp + off)         = make_uint4(hi[0], hi[1], hi[2], hi[3]);
                            *(uint4*)(zp + 16384 + off) = make_uint4(lo[0], lo[1], lo[2], lo[3]);
                        }
                    } else {
                        const float xv = xbuf[(size_t)bq * 4096 + it * 32 + dd];
#pragma unroll
                        for (int i = 0; i < 8; i++) {
                            float z[8];
#pragma unroll
                            for (int j = 0; j < 8; j++)
                                z[j] = xv * ip[(i * 8 + j) * 32];
                            uint32_t hi[4], lo[4];
#pragma unroll
                            for (int p = 0; p < 4; p++)
                                split2(z[2 * p], z[2 * p + 1], hi[p], lo[p]);
                            uint32_t off = zrow + ((16u * i) ^ zmask);
                            *(uint4*)(zp + off)         = make_uint4(hi[0], hi[1], hi[2], hi[3]);
                            *(uint4*)(zp + 16384 + off) = make_uint4(lo[0], lo[1], lo[2], lo[3]);
                        }
                    }
                }
                asm volatile("cp.async.wait_group 0;");
                __syncwarp();
                if (lane == 0) MBAR_ARRIVE(FULLB + 8 * s);
            }
        };

        produce((const char*)g_W0, NT0, true);
        __syncthreads();                       // L0 epilogue -> xbuf = x1
        produce((const char*)g_W1, NT12, false);
        __syncthreads();                       // L1 epilogue -> xbuf = x2
        produce((const char*)g_W2, NT12, false);
        __syncthreads();
        return;
    }

    // ==================== CONSUMERS (warps 0-7), m32 x n64 ====================
    const int wm = w & 3;
    const int wn = w >> 2;

    const int g = lane >> 3;
    const uint32_t maskL = (uint32_t)((lane & 7) << 4);
    uint32_t aRow[2], bRow[4], aCol[4], bCol[4];
#pragma unroll
    for (int mi = 0; mi < 2; mi++)
        aRow[mi] = (uint32_t)((32 * wm + 16 * mi + (lane & 7) + (g & 1) * 8) * 128);
#pragma unroll
    for (int p = 0; p < 4; p++)
        bRow[p] = (uint32_t)((64 * wn + 16 * p + 8 * ((g >> 1) & 1) + (lane & 7)) * 128);
#pragma unroll
    for (int kk = 0; kk < 4; kk++) {
        aCol[kk] = ((uint32_t)(((g >> 1) & 1) * 16 + 32 * kk)) ^ maskL;
        bCol[kk] = ((uint32_t)((g & 1) * 16 + 32 * kk)) ^ maskL;
    }

    float C[2][8][4];
    int gt = 0;

    auto zeroC = [&]() {
#pragma unroll
        for (int i = 0; i < 2; i++)
#pragma unroll
            for (int j = 0; j < 8; j++)
#pragma unroll
                for (int q = 0; q < 4; q++) C[i][j][q] = 0.f;
    };

    // Double-buffered per-k-step fragments: [buf][...]
    uint32_t ah[2][2][4], al[2][2][4], bh[2][4][4], bl[2][4][4];

    auto consume = [&](int ntiles) {
        for (int t = 0; t < ntiles; ++t, ++gt) {
            const int s = gt & 1;
            MBAR_WAIT(FULLB + 8 * s, (uint32_t)((gt >> 1) & 1));
            const uint32_t st = sb + STAGE_OFF + s * 65536;

            // prologue: load kk=0 into buf 0
#pragma unroll
            for (int mi = 0; mi < 2; mi++) {
                ldsm4(ah[0][mi], st + aRow[mi] + aCol[0]);
                ldsm4(al[0][mi], st + 16384 + aRow[mi] + aCol[0]);
            }
#pragma unroll
            for (int p = 0; p < 4; p++) {
                ldsm4(bh[0][p], st + 32768 + bRow[p] + bCol[0]);
                ldsm4(bl[0][p], st + 49152 + bRow[p] + bCol[0]);
            }
#pragma unroll
            for (int kk = 0; kk < 4; kk++) {
                const int cur = kk & 1, nxt = cur ^ 1;
                if (kk < 3) {
#pragma unroll
                    for (int mi = 0; mi < 2; mi++) {
                        ldsm4(ah[nxt][mi], st + aRow[mi] + aCol[kk + 1]);
                        ldsm4(al[nxt][mi], st + 16384 + aRow[mi] + aCol[kk + 1]);
                    }
#pragma unroll
                    for (int p = 0; p < 4; p++) {
                        ldsm4(bh[nxt][p], st + 32768 + bRow[p] + bCol[kk + 1]);
                        ldsm4(bl[nxt][p], st + 49152 + bRow[p] + bCol[kk + 1]);
                    }
                }
                // term-major MMA from buf `cur`
#pragma unroll
                for (int p = 0; p < 4; p++)
#pragma unroll
                    for (int mi = 0; mi < 2; mi++)
#pragma unroll
                        for (int q = 0; q < 2; q++)
                            mma_bf16(C[mi][2 * p + q], ah[cur][mi],
                                     bh[cur][p][2 * q], bh[cur][p][2 * q + 1]);
#pragma unroll
                for (int p = 0; p < 4; p++)
#pragma unroll
                    for (int mi = 0; mi < 2; mi++)
#pragma unroll
                        for (int q = 0; q < 2; q++)
                            mma_bf16(C[mi][2 * p + q], ah[cur][mi],
                                     bl[cur][p][2 * q], bl[cur][p][2 * q + 1]);
#pragma unroll
                for (int p = 0; p < 4; p++)
#pragma unroll
                    for (int mi = 0; mi < 2; mi++)
#pragma unroll
                        for (int q = 0; q < 2; q++)
                            mma_bf16(C[mi][2 * p + q], al[cur][mi],
                                     bh[cur][p][2 * q], bh[cur][p][2 * q + 1]);
            }
            __syncwarp();
            if (lane == 0) MBAR_ARRIVE(EMPTYB + 8 * s);
        }
    };

    const int mrow = lane >> 2;
    const int qn   = lane & 3;
    auto epilogue = [&](const float* bias, int out_off, bool write_x) {
#pragma unroll
        for (int mi = 0; mi < 2; mi++) {
#pragma unroll
            for (int h2 = 0; h2 < 2; h2++) {
                const int o = 32 * wm + 16 * mi + 8 * h2 + mrow;
                const float bv = __ldg(bias + o);
#pragma unroll
                for (int bl2 = 0; bl2 < 2; bl2++) {
                    const int bq = 2 * wn + bl2;
                    float sum = 0.f;
#pragma unroll
                    for (int jj = 0; jj < 4; jj++) {
                        const int j = 4 * bl2 + jj;
                        float v0 = fmaxf(C[mi][j][2 * h2]     + bv, 0.f);
                        float v1 = fmaxf(C[mi][j][2 * h2 + 1] + bv, 0.f);
                        sum += v0 + v1;
                        if (write_x) {
                            const int d = 8 * jj + 2 * qn;
                            *(float2*)(xbuf + ((size_t)bq * 128 + o) * 32 + d) =
                                make_float2(v0, v1);
                        }
                    }
                    sum += __shfl_xor_sync(0xffffffffu, sum, 1);
                    sum += __shfl_xor_sync(0xffffffffu, sum, 2);
                    if (qn == 0)
                        out[(size_t)(b0 + bq) * 384 + out_off + o] = sum;
                }
            }
        }
    };

    zeroC();
    consume(NT0);
    epilogue(bias0, 0, true);
    __syncthreads();

    zeroC();
    consume(NT12);
    epilogue(bias1, 128, true);
    __syncthreads();

    zeroC();
    consume(NT12);
    epilogue(bias2, 256, false);
    __syncthreads();
}

// ---------------------------------------------------------------------------
extern "C" void kernel_launch(void* const* d_in, const int* in_sizes, int n_in,
                              void* d_out, int out_size)
{
    (void)in_sizes; (void)n_in; (void)out_size;
    const float* input = (const float*)d_in[0];
    const float* W0    = (const float*)d_in[1];
    const float* b0    = (const float*)d_in[2];
    const float* W1    = (const float*)d_in[3];
    const float* b1    = (const float*)d_in[4];
    const float* W2    = (const float*)d_in[5];
    const float* b2    = (const float*)d_in[6];
    float* out = (float*)d_out;

    cudaFuncSetAttribute(fused3, cudaFuncAttributeMaxDynamicSharedMemorySize,
                         SMEM_TOTAL);

    prep_all<<<PREP_BLOCKS, 256>>>(W0, W1, W2);
    fused3<<<128, 320, SMEM_TOTAL>>>(input, b0, b1, b2, out);
}

// round 17
// speedup vs baseline: 1.1396x; 1.1396x over previous
#include <cuda_runtime.h>
#include <cuda_bf16.h>
#include <cstdint>
#include <cstddef>

// ---------------------------------------------------------------------------
// pre[b,o,d] = sum_{h,f} W[o, h*64+f] * x[b,h,d] * inp[b,f,d] + bias[o]
// x_next = relu(pre);  out[:, off+o] = sum_d relu(pre);  3 chained layers.
// B=512, F=64, D=32, O=128.
//
// Round-17 = round-14 winner (590.6us) + merged single prep kernel ONLY.
// Round-16 post-mortem: cutting producers 4->2 warps made producers the
// critical path (tensor 67->62%) -- reverted. One lever per round.
//  - fused3: 384 threads = 8 consumer warps (m32xn64, term-major 3-MMA bf16
//    split) + 4 producer warps (1 column each, ipreg inp cache).
//  - Fully fused L0->L1->L2 per CTA, x_next in SMEM, layer-0 symmetry fold,
//    2-stage mbarrier pipeline, continuous tile counter.
//  - prep_all: one launch (W0-fold / W1 / W2 / pair table by block range).
// ---------------------------------------------------------------------------

#define SW128(o) ((o) ^ (((o) >> 3) & 0x70))

#define K0SYM   2112
#define K0REAL  2080
#define NT0     33
#define NT12    128

__device__ uint4 g_W0[33 * 32768 / 16];
__device__ uint4 g_W1[128 * 8192 * 4 / 16];
__device__ uint4 g_W2[128 * 8192 * 4 / 16];
__device__ unsigned short g_pair[K0SYM];

__device__ __forceinline__ uint32_t smem_u32(const void* p) {
    uint32_t a;
    asm("{ .reg .u64 t; cvta.to.shared.u64 t, %1; cvt.u32.u64 %0, t; }"
        : "=r"(a) : "l"(p));
    return a;
}

__device__ __forceinline__ void split2(float z0, float z1,
                                       uint32_t& hi, uint32_t& lo) {
    __nv_bfloat162 h = __floats2bfloat162_rn(z0, z1);
    float2 hf = __bfloat1622float2(h);
    __nv_bfloat162 l = __floats2bfloat162_rn(z0 - hf.x, z1 - hf.y);
    hi = reinterpret_cast<uint32_t&>(h);
    lo = reinterpret_cast<uint32_t&>(l);
}

__device__ __forceinline__ void ldsm4(uint32_t r[4], uint32_t addr) {
    asm volatile("ldmatrix.sync.aligned.m8n8.x4.shared.b16 {%0,%1,%2,%3}, [%4];"
                 : "=r"(r[0]), "=r"(r[1]), "=r"(r[2]), "=r"(r[3]) : "r"(addr));
}

__device__ __forceinline__ void mma_bf16(float c[4], const uint32_t a[4],
                                         uint32_t b0, uint32_t b1) {
    asm volatile(
        "mma.sync.aligned.m16n8k16.row.col.f32.bf16.bf16.f32 "
        "{%0,%1,%2,%3}, {%4,%5,%6,%7}, {%8,%9}, {%0,%1,%2,%3};"
        : "+f"(c[0]), "+f"(c[1]), "+f"(c[2]), "+f"(c[3])
        : "r"(a[0]), "r"(a[1]), "r"(a[2]), "r"(a[3]), "r"(b0), "r"(b1));
}

#define MBAR_INIT(a, c) \
    asm volatile("mbarrier.init.shared.b64 [%0], %1;" :: "r"(a), "r"(c) : "memory")
#define MBAR_ARRIVE(a) \
    asm volatile("mbarrier.arrive.release.cta.shared::cta.b64 _, [%0];" :: "r"(a) : "memory")
#define MBAR_WAIT(a, p) do { uint32_t _m = (a); uint32_t _p = (p); uint32_t _d;      \
    asm volatile("{\n\t.reg .pred q;\n\t"                                            \
        "mbarrier.try_wait.parity.acquire.cta.shared::cta.b64 q, [%1], %2;\n\t"      \
        "selp.b32 %0,1,0,q;\n\t}" : "=r"(_d) : "r"(_m), "r"(_p) : "memory");         \
    if (!_d) {                                                                       \
        asm volatile("{\n\t.reg .pred q;\n\t"                                        \
            "WL%=:\n\t"                                                              \
            "mbarrier.try_wait.parity.acquire.cta.shared::cta.b64 q, [%0], %1, 0x989680;\n\t" \
            "@q bra.uni WD%=;\n\t"                                                   \
            "bra.uni WL%=;\n\t"                                                      \
            "WD%=:\n\t}" :: "r"(_m), "r"(_p) : "memory");                            \
    } } while (0)

// --------------------------- merged prep kernel -----------------------------
// Block ranges: [0,132) W0-fold; [132,644) W1; [644,1156) W2; [1156,1165) pairs
#define PREP_BLOCKS 1165

__device__ __forceinline__ void prep_chunk(const float* __restrict__ Wrow8,
                                           char* __restrict__ base,
                                           int o, int k0) {
    const float4* src = (const float4*)Wrow8;
    float4 v0 = src[0], v1 = src[1];
    float zf[8] = {v0.x, v0.y, v0.z, v0.w, v1.x, v1.y, v1.z, v1.w};
    uint32_t hi[4], lo[4];
#pragma unroll
    for (int p = 0; p < 4; p++) split2(zf[2 * p], zf[2 * p + 1], hi[p], lo[p]);
    char* tile = base + (size_t)(k0 >> 6) * 32768;
    uint32_t off = SW128((uint32_t)(o * 128 + (k0 & 63) * 2));
    *(uint4*)(tile + off)         = make_uint4(hi[0], hi[1], hi[2], hi[3]);
    *(uint4*)(tile + 16384 + off) = make_uint4(lo[0], lo[1], lo[2], lo[3]);
}

__global__ __launch_bounds__(256)
void prep_all(const float* __restrict__ W0,
              const float* __restrict__ W1,
              const float* __restrict__ W2)
{
    const int blk = blockIdx.x;
    const int t   = threadIdx.x;
    if (blk < 132) {
        int idx = blk * 256 + t;
        if (idx >= 128 * (K0SYM / 8)) return;
        int o  = idx / (K0SYM / 8);
        int k0 = (idx % (K0SYM / 8)) * 8;
        const float* Wo = W0 + (size_t)o * 4096;
        float zf[8];
#pragma unroll
        for (int tt = 0; tt < 8; tt++) {
            int k = k0 + tt;
            float c = 0.f;
            if (k < K0REAL) {
                int i = 0, base = 0;
                while (base + (64 - i) <= k) { base += 64 - i; i++; }
                int j = i + (k - base);
                c = (i == j) ? Wo[i * 65] : (Wo[i * 64 + j] + Wo[j * 64 + i]);
            }
            zf[tt] = c;
        }
        uint32_t hi[4], lo[4];
#pragma unroll
        for (int p = 0; p < 4; p++) split2(zf[2 * p], zf[2 * p + 1], hi[p], lo[p]);
        char* tile = (char*)g_W0 + (size_t)(k0 >> 6) * 32768;
        uint32_t off = SW128((uint32_t)(o * 128 + (k0 & 63) * 2));
        *(uint4*)(tile + off)         = make_uint4(hi[0], hi[1], hi[2], hi[3]);
        *(uint4*)(tile + 16384 + off) = make_uint4(lo[0], lo[1], lo[2], lo[3]);
    } else if (blk < 1156) {
        const bool is1 = blk < 644;
        const float* W  = is1 ? W1 : W2;
        char* dst       = (char*)(is1 ? g_W1 : g_W2);
        int idx = (blk - (is1 ? 132 : 644)) * 256 + t;
        int o = idx >> 10;
        int k = (idx & 1023) * 8;
        prep_chunk(W + (size_t)o * 8192 + k, dst, o, k);
    } else {
        int k = (blk - 1156) * 256 + t;
        if (k >= K0SYM) return;
        if (k < K0REAL) {
            int i = 0, base = 0;
            while (base + (64 - i) <= k) { base += 64 - i; i++; }
            int j = i + (k - base);
            g_pair[k] = (unsigned short)(i | (j << 8));
        } else {
            g_pair[k] = 0;
        }
    }
}

// --------------------------- fused 3-layer kernel ---------------------------
// SMEM: [0,32768) inp_s; [32768,98304) xbuf; [98304 + s*65536) stages;
//       [229376,229408) mbarriers
#define XBUF_OFF   32768
#define STAGE_OFF  98304
#define MB_OFF     229376
#define SMEM_TOTAL 229408

__global__ __launch_bounds__(384, 1)
void fused3(const float* __restrict__ inp,
            const float* __restrict__ bias0,
            const float* __restrict__ bias1,
            const float* __restrict__ bias2,
            float* __restrict__ out)
{
    extern __shared__ char smem[];
    const uint32_t sb = smem_u32(smem);
    float* inp_s = (float*)smem;
    float* xbuf  = (float*)(smem + XBUF_OFF);
    const int tid  = threadIdx.x;
    const int lane = tid & 31;
    const int w    = tid >> 5;
    const int b0   = blockIdx.x * 4;

    const uint32_t FULLB  = sb + MB_OFF;        // +8*s
    const uint32_t EMPTYB = sb + MB_OFF + 16;   // +8*s

    if (tid == 0) {
#pragma unroll
        for (int s = 0; s < 2; s++) {
            MBAR_INIT(FULLB + 8 * s, 4);     // 4 producer warps
            MBAR_INIT(EMPTYB + 8 * s, 8);    // 8 consumer warps
        }
    }
    {   // stage inp (2048 float4, 384 threads)
        const float4* src = (const float4*)(inp + (size_t)b0 * 2048);
        float4* dst = (float4*)inp_s;
        for (int i = tid; i < 2048; i += 384) dst[i] = src[i];
    }
    __syncthreads();

    if (w >= 8) {
        // ==================== PRODUCERS (warps 8-11) ====================
        const int n  = tid - 256;                  // 0..127
        const int bq = n >> 5;
        const int dd = n & 31;
        const float* ip = inp_s + (size_t)bq * 2048 + dd;
        const float* xp = xbuf + (size_t)bq * 4096 + dd;     // + it*32
        const uint32_t zrow  = (uint32_t)n * 128;
        const uint32_t zmask = (uint32_t)((n & 7) << 4);

        // Register-cache inp column (f = 0..63); Z index is compile-time in
        // the unrolled loops below so this never spills to local.
        float ipreg[64];
#pragma unroll
        for (int k = 0; k < 64; k++) ipreg[k] = ip[k * 32];

        int gt = 0;   // continuous tile counter across all layers

        auto produce = [&](const char* gW, int ntiles, bool sym) {
            for (int it = 0; it < ntiles; ++it, ++gt) {
                const int s = gt & 1;
                if (gt >= 2) MBAR_WAIT(EMPTYB + 8 * s,
                                       (uint32_t)(((gt >> 1) - 1) & 1));
                // W tile (128 thr x 256 B)
                {
                    uint32_t dsb = sb + STAGE_OFF + s * 65536 + n * 16;
                    const char* srcW = gW + (size_t)it * 32768 + n * 16;
#pragma unroll
                    for (int i = 0; i < 16; i++)
                        asm volatile("cp.async.cg.shared.global [%0], [%1], 16;"
                                     :: "r"(dsb + i * 2048), "l"(srcW + i * 2048));
                    asm volatile("cp.async.commit_group;");
                }
                // Z tile
                char* zp = smem + STAGE_OFF + s * 65536 + 32768;
                if (sym) {
#pragma unroll
                    for (int i = 0; i < 8; i++) {
                        float z[8];
#pragma unroll
                        for (int j = 0; j < 8; j++) {
                            int pr = __ldg(&g_pair[it * 64 + i * 8 + j]);
                            z[j] = ip[(pr & 255) * 32] * ip[(pr >> 8) * 32];
                        }
                        uint32_t hi[4], lo[4];
#pragma unroll
                        for (int p = 0; p < 4; p++)
                            split2(z[2 * p], z[2 * p + 1], hi[p], lo[p]);
                        uint32_t off = zrow + ((16u * i) ^ zmask);
                        *(uint4*)(zp + off)         = make_uint4(hi[0], hi[1], hi[2], hi[3]);
                        *(uint4*)(zp + 16384 + off) = make_uint4(lo[0], lo[1], lo[2], lo[3]);
                    }
                } else {
                    const float xv = xp[it * 32];    // x from SMEM xbuf
#pragma unroll
                    for (int i = 0; i < 8; i++) {
                        float z[8];
#pragma unroll
                        for (int j = 0; j < 8; j++) z[j] = xv * ipreg[i * 8 + j];
                        uint32_t hi[4], lo[4];
#pragma unroll
                        for (int p = 0; p < 4; p++)
                            split2(z[2 * p], z[2 * p + 1], hi[p], lo[p]);
                        uint32_t off = zrow + ((16u * i) ^ zmask);
                        *(uint4*)(zp + off)         = make_uint4(hi[0], hi[1], hi[2], hi[3]);
                        *(uint4*)(zp + 16384 + off) = make_uint4(lo[0], lo[1], lo[2], lo[3]);
                    }
                }
                asm volatile("cp.async.wait_group 0;");
                __syncwarp();
                if (lane == 0) MBAR_ARRIVE(FULLB + 8 * s);
            }
        };

        produce((const char*)g_W0, NT0, true);
        __syncthreads();                       // L0 epilogue -> xbuf = x1
        produce((const char*)g_W1, NT12, false);
        __syncthreads();                       // L1 epilogue -> xbuf = x2
        produce((const char*)g_W2, NT12, false);
        __syncthreads();
        return;
    }

    // ==================== CONSUMERS (warps 0-7), m32 x n64 ====================
    const int wm = w & 3;
    const int wn = w >> 2;

    const int g = lane >> 3;
    const uint32_t maskL = (uint32_t)((lane & 7) << 4);
    uint32_t aRow[2], bRow[4], aCol[4], bCol[4];
#pragma unroll
    for (int mi = 0; mi < 2; mi++)
        aRow[mi] = (uint32_t)((32 * wm + 16 * mi + (lane & 7) + (g & 1) * 8) * 128);
#pragma unroll
    for (int p = 0; p < 4; p++)
        bRow[p] = (uint32_t)((64 * wn + 16 * p + 8 * ((g >> 1) & 1) + (lane & 7)) * 128);
#pragma unroll
    for (int kk = 0; kk < 4; kk++) {
        aCol[kk] = ((uint32_t)(((g >> 1) & 1) * 16 + 32 * kk)) ^ maskL;
        bCol[kk] = ((uint32_t)((g & 1) * 16 + 32 * kk)) ^ maskL;
    }

    float C[2][8][4];
    int gt = 0;

    auto zeroC = [&]() {
#pragma unroll
        for (int i = 0; i < 2; i++)
#pragma unroll
            for (int j = 0; j < 8; j++)
#pragma unroll
                for (int q = 0; q < 4; q++) C[i][j][q] = 0.f;
    };

    auto consume = [&](int ntiles) {
        for (int t = 0; t < ntiles; ++t, ++gt) {
            const int s = gt & 1;
            MBAR_WAIT(FULLB + 8 * s, (uint32_t)((gt >> 1) & 1));
            const uint32_t st = sb + STAGE_OFF + s * 65536;
#pragma unroll
            for (int kk = 0; kk < 4; kk++) {
                uint32_t ah[2][4], al[2][4], bh[4][4], bl[4][4];
#pragma unroll
                for (int mi = 0; mi < 2; mi++) {
                    ldsm4(ah[mi], st + aRow[mi] + aCol[kk]);
                    ldsm4(al[mi], st + 16384 + aRow[mi] + aCol[kk]);
                }
#pragma unroll
                for (int p = 0; p < 4; p++) {
                    ldsm4(bh[p], st + 32768 + bRow[p] + bCol[kk]);
                    ldsm4(bl[p], st + 49152 + bRow[p] + bCol[kk]);
                }
#pragma unroll
                for (int p = 0; p < 4; p++)
#pragma unroll
                    for (int mi = 0; mi < 2; mi++)
#pragma unroll
                        for (int q = 0; q < 2; q++)
                            mma_bf16(C[mi][2 * p + q], ah[mi],
                                     bh[p][2 * q], bh[p][2 * q + 1]);
#pragma unroll
                for (int p = 0; p < 4; p++)
#pragma unroll
                    for (int mi = 0; mi < 2; mi++)
#pragma unroll
                        for (int q = 0; q < 2; q++)
                            mma_bf16(C[mi][2 * p + q], ah[mi],
                                     bl[p][2 * q], bl[p][2 * q + 1]);
#pragma unroll
                for (int p = 0; p < 4; p++)
#pragma unroll
                    for (int mi = 0; mi < 2; mi++)
#pragma unroll
                        for (int q = 0; q < 2; q++)
                            mma_bf16(C[mi][2 * p + q], al[mi],
                                     bh[p][2 * q], bh[p][2 * q + 1]);
            }
            __syncwarp();
            if (lane == 0) MBAR_ARRIVE(EMPTYB + 8 * s);
        }
    };

    const int mrow = lane >> 2;
    const int qn   = lane & 3;
    auto epilogue = [&](const float* bias, int out_off, bool write_x) {
#pragma unroll
        for (int mi = 0; mi < 2; mi++) {
#pragma unroll
            for (int h2 = 0; h2 < 2; h2++) {
                const int o = 32 * wm + 16 * mi + 8 * h2 + mrow;
                const float bv = __ldg(bias + o);
#pragma unroll
                for (int bl2 = 0; bl2 < 2; bl2++) {
                    const int bq = 2 * wn + bl2;
                    float sum = 0.f;
#pragma unroll
                    for (int jj = 0; jj < 4; jj++) {
                        const int j = 4 * bl2 + jj;
                        float v0 = fmaxf(C[mi][j][2 * h2]     + bv, 0.f);
                        float v1 = fmaxf(C[mi][j][2 * h2 + 1] + bv, 0.f);
                        sum += v0 + v1;
                        if (write_x) {
                            const int d = 8 * jj + 2 * qn;
                            *(float2*)(xbuf + ((size_t)bq * 128 + o) * 32 + d) =
                                make_float2(v0, v1);
                        }
                    }
                    sum += __shfl_xor_sync(0xffffffffu, sum, 1);
                    sum += __shfl_xor_sync(0xffffffffu, sum, 2);
                    if (qn == 0)
                        out[(size_t)(b0 + bq) * 384 + out_off + o] = sum;
                }
            }
        }
    };

    zeroC();
    consume(NT0);
    epilogue(bias0, 0, true);
    __syncthreads();

    zeroC();
    consume(NT12);
    epilogue(bias1, 128, true);
    __syncthreads();

    zeroC();
    consume(NT12);
    epilogue(bias2, 256, false);
    __syncthreads();
}

// ---------------------------------------------------------------------------
extern "C" void kernel_launch(void* const* d_in, const int* in_sizes, int n_in,
                              void* d_out, int out_size)
{
    (void)in_sizes; (void)n_in; (void)out_size;
    const float* input = (const float*)d_in[0];
    const float* W0    = (const float*)d_in[1];
    const float* b0    = (const float*)d_in[2];
    const float* W1    = (const float*)d_in[3];
    const float* b1    = (const float*)d_in[4];
    const float* W2    = (const float*)d_in[5];
    const float* b2    = (const float*)d_in[6];
    float* out = (float*)d_out;

    cudaFuncSetAttribute(fused3, cudaFuncAttributeMaxDynamicSharedMemorySize,
                         SMEM_TOTAL);

    prep_all<<<PREP_BLOCKS, 256>>>(W0, W1, W2);
    fused3<<<128, 384, SMEM_TOTAL>>>(input, b0, b1, b2, out);
}